// round 1
// baseline (speedup 1.0000x reference)
#include <cuda_runtime.h>
#include <cstdint>

#define KK 24
#define BC 14
#define TT 512
#define BATCH 2048

// Global scratch (device globals: no allocation allowed)
__device__ double g_acc;
__device__ int g_start;
__device__ int g_tag64;

// ---- packed f32x2 helpers (Blackwell) ----
static __device__ __forceinline__ unsigned long long fma2(unsigned long long a, unsigned long long b, unsigned long long c) {
    unsigned long long d;
    asm("fma.rn.f32x2 %0, %1, %2, %3;" : "=l"(d) : "l"(a), "l"(b), "l"(c));
    return d;
}
static __device__ __forceinline__ unsigned long long mul2(unsigned long long a, unsigned long long b) {
    unsigned long long d;
    asm("mul.rn.f32x2 %0, %1, %2;" : "=l"(d) : "l"(a), "l"(b));
    return d;
}
static __device__ __forceinline__ void upk(unsigned long long v, float& lo, float& hi) {
    asm("mov.b64 {%0, %1}, %2;" : "=f"(lo), "=f"(hi) : "l"(v));
}
static __device__ __forceinline__ unsigned long long pk(float lo, float hi) {
    unsigned long long r;
    asm("mov.b64 %0, {%1, %2};" : "=l"(r) : "f"(lo), "f"(hi));
    return r;
}

// ---- init: zero accumulator, read start id, detect tag dtype ----
__global__ void init_kernel(const void* __restrict__ tags, const int* __restrict__ startp) {
    g_acc = 0.0;
    g_start = startp[0];  // low 32-bit word: correct for LE int32 or int64
    // int64 detection: values are in [0,22), so every high word is 0 iff int64.
    const unsigned int* w = (const unsigned int*)tags;
    int is64 = 1;
    for (int i = 0; i < 128; ++i) {
        if (w[2 * i + 1] != 0u) { is64 = 0; break; }
    }
    g_tag64 = is64;
}

// ---- main forward recursion ----
// thread (j = state, bl = local batch); v in shared (double buffered);
// E row j in 12 packed regs; linear-space recursion with periodic renorm.
__global__ __launch_bounds__(KK * BC) void crf_forward_kernel(const float* __restrict__ feats,
                                                              const float* __restrict__ trans) {
    __shared__ __align__(16) float vs[2][BC][KK];
    __shared__ float fsh[BC];
    const int tid = threadIdx.x;
    const int j = tid % KK;
    const int bl = tid / KK;
    const int bg = blockIdx.x * BC + bl;
    const int bgc = (bg < BATCH) ? bg : (BATCH - 1);

    // E2[k] = (exp(trans[j, 2k]), exp(trans[j, 2k+1]))
    unsigned long long E2[12];
#pragma unroll
    for (int k = 0; k < 12; ++k) {
        float e0 = __expf(trans[j * KK + 2 * k]);
        float e1 = __expf(trans[j * KK + 2 * k + 1]);
        E2[k] = pk(e0, e1);
    }

    // v0: 1 at start label, 0 elsewhere (exp of {0, -1e4})
    vs[0][bl][j] = (j == g_start) ? 1.0f : 0.0f;
    float s = 0.0f;  // accumulated log scale

    const float* fb = feats + bgc * (TT * KK) + j;
    // software-pipelined feat prefetch, distance 8
    float f[8];
#pragma unroll
    for (int r = 0; r < 8; ++r) f[r] = __ldg(fb + (1 + r) * KK);
    __syncthreads();

    int cur = 0;
#pragma unroll 1
    for (int t = 1; t < TT; t += 8) {
#pragma unroll
        for (int r = 0; r < 8; ++r) {
            const int tt = t + r;
            if (tt < TT) {  // uniform branch
                float fnew = 0.0f;
                if (tt + 8 < TT) fnew = __ldg(fb + (tt + 8) * KK);

                const ulonglong2* vp = reinterpret_cast<const ulonglong2*>(&vs[cur][bl][0]);
                ulonglong2 q0 = vp[0], q1 = vp[1], q2 = vp[2];
                ulonglong2 q3 = vp[3], q4 = vp[4], q5 = vp[5];

                unsigned long long acc_a = mul2(E2[0], q0.x);
                unsigned long long acc_b = mul2(E2[1], q0.y);
                acc_a = fma2(E2[2], q1.x, acc_a);
                acc_b = fma2(E2[3], q1.y, acc_b);
                acc_a = fma2(E2[4], q2.x, acc_a);
                acc_b = fma2(E2[5], q2.y, acc_b);
                acc_a = fma2(E2[6], q3.x, acc_a);
                acc_b = fma2(E2[7], q3.y, acc_b);
                acc_a = fma2(E2[8], q4.x, acc_a);
                acc_b = fma2(E2[9], q4.y, acc_b);
                acc_a = fma2(E2[10], q5.x, acc_a);
                acc_b = fma2(E2[11], q5.y, acc_b);

                float a0, a1, b0, b1;
                upk(acc_a, a0, a1);
                upk(acc_b, b0, b1);
                float dot = (a0 + a1) + (b0 + b1);
                float ef = __expf(f[r]);
                float vnew;
                if (((r & 3) == 0) && (tt > 1)) {
                    // renorm every 4 steps: max over the 24 v values (all threads
                    // of a batch read identical data -> identical m, no comm needed)
                    float x0, x1, x2, x3, m;
                    upk(q0.x, x0, x1); upk(q0.y, x2, x3);
                    m = fmaxf(fmaxf(x0, x1), fmaxf(x2, x3));
                    upk(q1.x, x0, x1); upk(q1.y, x2, x3);
                    m = fmaxf(m, fmaxf(fmaxf(x0, x1), fmaxf(x2, x3)));
                    upk(q2.x, x0, x1); upk(q2.y, x2, x3);
                    m = fmaxf(m, fmaxf(fmaxf(x0, x1), fmaxf(x2, x3)));
                    upk(q3.x, x0, x1); upk(q3.y, x2, x3);
                    m = fmaxf(m, fmaxf(fmaxf(x0, x1), fmaxf(x2, x3)));
                    upk(q4.x, x0, x1); upk(q4.y, x2, x3);
                    m = fmaxf(m, fmaxf(fmaxf(x0, x1), fmaxf(x2, x3)));
                    upk(q5.x, x0, x1); upk(q5.y, x2, x3);
                    m = fmaxf(m, fmaxf(fmaxf(x0, x1), fmaxf(x2, x3)));
                    float inv = 1.0f / m;
                    vnew = dot * ef * inv;
                    s += __logf(m);
                } else {
                    vnew = dot * ef;
                }
                vs[cur ^ 1][bl][j] = vnew;
                f[r] = fnew;
            }
            __syncthreads();
            if (tt < TT) cur ^= 1;
        }
    }

    // forward score per batch: log(sum v) + s
    if (j == 0 && bg < BATCH) {
        float sum = 0.0f;
#pragma unroll
        for (int i = 0; i < KK; ++i) sum += vs[cur][bl][i];
        fsh[bl] = __logf(sum) + s;
    }
    __syncthreads();
    if (tid == 0) {
        int nb = BATCH - blockIdx.x * BC;
        if (nb > BC) nb = BC;
        double part = 0.0;
        for (int b = 0; b < nb; ++b) part += (double)fsh[b];
        atomicAdd(&g_acc, part);
    }
}

// ---- gold (numerator) score: sum_t trans[tag_t, tag_{t-1}] + feat[b,t,tag_t] ----
__global__ void gold_kernel(const float* __restrict__ feats, const float* __restrict__ trans,
                            const void* __restrict__ tags) {
    const int NE = BATCH * (TT - 1);
    int e = blockIdx.x * blockDim.x + threadIdx.x;
    float c = 0.0f;
    if (e < NE) {
        int b = e / (TT - 1);
        int tt = 1 + (e - b * (TT - 1));
        int it, ip;
        if (g_tag64) {
            const long long* tg = (const long long*)tags;
            it = (int)tg[b * TT + tt];
            ip = (int)tg[b * TT + tt - 1];
        } else {
            const int* tg = (const int*)tags;
            it = tg[b * TT + tt];
            ip = tg[b * TT + tt - 1];
        }
        c = trans[it * KK + ip] + feats[(b * TT + tt) * KK + it];
    }
#pragma unroll
    for (int o = 16; o > 0; o >>= 1) c += __shfl_down_sync(0xffffffffu, c, o);
    __shared__ float ws[8];
    int lane = threadIdx.x & 31, wid = threadIdx.x >> 5;
    if (lane == 0) ws[wid] = c;
    __syncthreads();
    if (threadIdx.x == 0) {
        float sblk = 0.0f;
        int nw = (int)(blockDim.x >> 5);
        for (int w2 = 0; w2 < nw; ++w2) sblk += ws[w2];
        atomicAdd(&g_acc, -(double)sblk);
    }
}

// ---- finalize: mean ----
__global__ void fin_kernel(float* __restrict__ out) {
    out[0] = (float)(g_acc * (1.0 / (double)BATCH));
}

extern "C" void kernel_launch(void* const* d_in, const int* in_sizes, int n_in,
                              void* d_out, int out_size) {
    const float* feats = (const float*)d_in[0];
    const float* trans = (const float*)d_in[1];
    const void* tags = d_in[2];
    const int* startp = (const int*)d_in[3];

    init_kernel<<<1, 1>>>(tags, startp);
    crf_forward_kernel<<<(BATCH + BC - 1) / BC, KK * BC>>>(feats, trans);
    const int ne = BATCH * (TT - 1);
    gold_kernel<<<(ne + 255) / 256, 256>>>(feats, trans, tags);
    fin_kernel<<<1, 1>>>((float*)d_out);
}

// round 2
// speedup vs baseline: 1.3122x; 1.3122x over previous
#include <cuda_runtime.h>
#include <cstdint>

#define KK 24
#define TT 512
#define BATCH 2048
#define WPC 8
#define THREADS (WPC * 32)
#define GRID (BATCH / WPC)

// per-batch partial scores (forward - gold); fully overwritten each call
__device__ float g_part[BATCH];

// ---- packed f32x2 helpers (Blackwell) ----
static __device__ __forceinline__ unsigned long long fma2(unsigned long long a, unsigned long long b, unsigned long long c) {
    unsigned long long d;
    asm("fma.rn.f32x2 %0, %1, %2, %3;" : "=l"(d) : "l"(a), "l"(b), "l"(c));
    return d;
}
static __device__ __forceinline__ unsigned long long mul2(unsigned long long a, unsigned long long b) {
    unsigned long long d;
    asm("mul.rn.f32x2 %0, %1, %2;" : "=l"(d) : "l"(a), "l"(b));
    return d;
}
static __device__ __forceinline__ void upk(unsigned long long v, float& lo, float& hi) {
    asm("mov.b64 {%0, %1}, %2;" : "=f"(lo), "=f"(hi) : "l"(v));
}
static __device__ __forceinline__ unsigned long long pk(float lo, float hi) {
    unsigned long long r;
    asm("mov.b64 %0, {%1, %2};" : "=l"(r) : "f"(lo), "f"(hi));
    return r;
}

// ---- main kernel: warp-per-batch forward recursion + fused gold score ----
__global__ __launch_bounds__(THREADS) void crf_kernel(const float* __restrict__ feats,
                                                      const float* __restrict__ trans,
                                                      const void* __restrict__ tags,
                                                      const int* __restrict__ startp) {
    __shared__ __align__(16) float vs[WPC][2][32];
    const int lane = threadIdx.x & 31;
    const int w = threadIdx.x >> 5;
    const int b = blockIdx.x * WPC + w;
    const int j = (lane < KK) ? lane : (KK - 1);  // clamp pad lanes

    const int start = startp[0];  // low 32-bit word valid for LE int32/int64

    // tag dtype detection: values in [0,22); if int64, all odd 32-bit words are 0.
    const unsigned int* wds = (const unsigned int*)tags;
    unsigned int hiw = wds[2 * lane + 1];
    const int is64 = (__ballot_sync(0xffffffffu, hiw != 0u) == 0u);

    // E row j: E2[k] = (exp(trans[j,2k]), exp(trans[j,2k+1]))
    unsigned long long E2[12];
#pragma unroll
    for (int k = 0; k < 12; ++k) {
        float e0 = __expf(trans[j * KK + 2 * k]);
        float e1 = __expf(trans[j * KK + 2 * k + 1]);
        E2[k] = pk(e0, e1);
    }

    // v0 one-hot at start label (pad cols get 0)
    vs[w][0][lane] = (lane == start) ? 1.0f : 0.0f;
    float s = 0.0f;     // accumulated log scale
    float gacc = 0.0f;  // gold partial (lanes 24-31)

    const float* fb = feats + b * (TT * KK) + j;
    float f[8];
#pragma unroll
    for (int r = 0; r < 8; ++r) f[r] = __ldg(fb + (1 + r) * KK);
    __syncwarp();

    const long long* tg64 = (const long long*)tags + b * TT;
    const int* tg32 = (const int*)tags + b * TT;
    const int gm = lane - 24;  // gold lane index 0..7 for lanes 24-31

    int cur = 0;
#pragma unroll 1
    for (int t = 1; t < TT; t += 8) {
#pragma unroll
        for (int r = 0; r < 8; ++r) {
            const int tt = t + r;
            if (tt < TT) {
                int pf = (tt + 8 < TT) ? (tt + 8) : (TT - 1);
                float fnew = __ldg(fb + pf * KK);

                const ulonglong2* vp = reinterpret_cast<const ulonglong2*>(&vs[w][cur][0]);
                ulonglong2 q0 = vp[0], q1 = vp[1], q2 = vp[2];
                ulonglong2 q3 = vp[3], q4 = vp[4], q5 = vp[5];

                unsigned long long acc_a = mul2(E2[0], q0.x);
                unsigned long long acc_b = mul2(E2[1], q0.y);
                acc_a = fma2(E2[2], q1.x, acc_a);
                acc_b = fma2(E2[3], q1.y, acc_b);
                acc_a = fma2(E2[4], q2.x, acc_a);
                acc_b = fma2(E2[5], q2.y, acc_b);
                acc_a = fma2(E2[6], q3.x, acc_a);
                acc_b = fma2(E2[7], q3.y, acc_b);
                acc_a = fma2(E2[8], q4.x, acc_a);
                acc_b = fma2(E2[9], q4.y, acc_b);
                acc_a = fma2(E2[10], q5.x, acc_a);
                acc_b = fma2(E2[11], q5.y, acc_b);

                float a0, a1, b0, b1;
                upk(acc_a, a0, a1);
                upk(acc_b, b0, b1);
                float dot = (a0 + a1) + (b0 + b1);
                float ef = __expf(f[r]);
                float vnew;
                if (((r & 3) == 0) && (tt > 1)) {
                    // renorm every 4 steps: max over the 24 v's (identical on all lanes)
                    float x0, x1, x2, x3, m;
                    upk(q0.x, x0, x1); upk(q0.y, x2, x3);
                    m = fmaxf(fmaxf(x0, x1), fmaxf(x2, x3));
                    upk(q1.x, x0, x1); upk(q1.y, x2, x3);
                    m = fmaxf(m, fmaxf(fmaxf(x0, x1), fmaxf(x2, x3)));
                    upk(q2.x, x0, x1); upk(q2.y, x2, x3);
                    m = fmaxf(m, fmaxf(fmaxf(x0, x1), fmaxf(x2, x3)));
                    upk(q3.x, x0, x1); upk(q3.y, x2, x3);
                    m = fmaxf(m, fmaxf(fmaxf(x0, x1), fmaxf(x2, x3)));
                    upk(q4.x, x0, x1); upk(q4.y, x2, x3);
                    m = fmaxf(m, fmaxf(fmaxf(x0, x1), fmaxf(x2, x3)));
                    upk(q5.x, x0, x1); upk(q5.y, x2, x3);
                    m = fmaxf(m, fmaxf(fmaxf(x0, x1), fmaxf(x2, x3)));
                    float inv = 1.0f / m;
                    vnew = dot * ef * inv;
                    s += __logf(m);
                } else {
                    vnew = dot * ef;
                }
                vs[w][cur ^ 1][lane] = vnew;
                f[r] = fnew;
                cur ^= 1;
            }
            __syncwarp();
        }
        // gold window: lanes 24-31 handle tts t..t+7 (feat rows are L1-resident)
        {
            const int gt = t + gm;
            if (lane >= 24 && gt < TT) {
                int it, ip;
                if (is64) {
                    it = (int)tg64[gt];
                    ip = (int)tg64[gt - 1];
                } else {
                    it = tg32[gt];
                    ip = tg32[gt - 1];
                }
                gacc += trans[it * KK + ip] + __ldg(feats + (b * TT + gt) * KK + it);
            }
        }
    }

    // forward score: log(sum v) + s   (identical across lanes)
    float sum = 0.0f;
#pragma unroll
    for (int i = 0; i < KK; ++i) sum += vs[w][cur][i];
    float fwd = __logf(sum) + s;

    // reduce gold across lanes (lanes 0-23 contribute 0)
#pragma unroll
    for (int o = 16; o > 0; o >>= 1) gacc += __shfl_xor_sync(0xffffffffu, gacc, o);

    if (lane == 0) g_part[b] = fwd - gacc;
}

// ---- final reduce: mean over batches ----
__global__ void reduce_kernel(float* __restrict__ out) {
    __shared__ double sh[256];
    const int tid = threadIdx.x;
    double a = 0.0;
    for (int k = tid; k < BATCH; k += 256) a += (double)g_part[k];
    sh[tid] = a;
    __syncthreads();
    for (int st = 128; st > 0; st >>= 1) {
        if (tid < st) sh[tid] += sh[tid + st];
        __syncthreads();
    }
    if (tid == 0) out[0] = (float)(sh[0] * (1.0 / (double)BATCH));
}

extern "C" void kernel_launch(void* const* d_in, const int* in_sizes, int n_in,
                              void* d_out, int out_size) {
    const float* feats = (const float*)d_in[0];
    const float* trans = (const float*)d_in[1];
    const void* tags = d_in[2];
    const int* startp = (const int*)d_in[3];

    crf_kernel<<<GRID, THREADS>>>(feats, trans, tags, startp);
    reduce_kernel<<<1, 256>>>((float*)d_out);
}